// round 8
// baseline (speedup 1.0000x reference)
#include <cuda_runtime.h>
#include <cuda_bf16.h>
#include <math.h>
#include <stdint.h>

// Problem constants
#define BATCH 32
#define TT 64
#define SS 64
#define VV 32000
#define EE 512
#define HH 512
#define NCTA 144

// ---------------- device scratch ----------------
__device__ float g_embF[2048 * 512];             // embedded fp32, row = t*32+b
__device__ float g_encproj[2048 * 512];          // enc @ W_a, row = b*64+s
__device__ float g_h[2 * BATCH * HH];            // fp32 state
__device__ float g_c[2 * BATCH * HH];
__device__ float g_ctxF[BATCH * 512];            // current context fp32
__device__ float g_feat[TT * BATCH * 1024];      // [t][b][ h1 | ctx ]
__device__ float g_embpre[TT * BATCH * 2048];    // emb @ Wih0[:, :512]^T
__device__ float g_g0hh[4 * BATCH * 2048];
__device__ float g_g1hh[4 * BATCH * 2048];
__device__ float g_g0ctx[8 * BATCH * 2048];
__device__ float g_g1ih[8 * BATCH * 2048];
__device__ unsigned g_barcnt;
// packed tf32 weights: [nt8][ki8(64)][lane32] uint4{bH0,bH1,bL0,bL1}
__device__ uint4 g_pkWaT[64 * 64 * 32];          // W_a^T (for encproj)
__device__ uint4 g_pkHH0[256 * 64 * 32];
__device__ uint4 g_pkHH1[256 * 64 * 32];
__device__ uint4 g_pkIH1[256 * 64 * 32];
__device__ uint4 g_pkIHC[256 * 64 * 32];
__device__ uint4 g_pkIH0[256 * 64 * 32];
// bf16 split operands for big projection GEMM
__device__ __nv_bfloat16 g_WH[VV * 1024];
__device__ __nv_bfloat16 g_WL[VV * 1024];
__device__ __nv_bfloat16 g_fH[2048 * 1024];
__device__ __nv_bfloat16 g_fL[2048 * 1024];

// ---------------- PTX helpers ----------------
__device__ __forceinline__ uint32_t smem_to_u32(const void* p) {
    uint32_t a;
    asm("{ .reg .u64 t; cvta.to.shared.u64 t, %1; cvt.u32.u64 %0, t; }" : "=r"(a) : "l"(p));
    return a;
}
#define CP16(dst, src) \
    asm volatile("cp.async.cg.shared.global [%0], [%1], 16;" \
                 :: "r"(dst), "l"(src) : "memory")
#define CP_COMMIT() asm volatile("cp.async.commit_group;" ::: "memory")
#define CP_WAIT0()  asm volatile("cp.async.wait_group 0;" ::: "memory")
#define CP_WAIT1()  asm volatile("cp.async.wait_group 1;" ::: "memory")

#define LDSM_X4(r0, r1, r2, r3, addr) \
    asm volatile("ldmatrix.sync.aligned.m8n8.x4.shared.b16 {%0,%1,%2,%3}, [%4];" \
                 : "=r"(r0), "=r"(r1), "=r"(r2), "=r"(r3) : "r"(addr))
#define LDSM_X2(r0, r1, addr) \
    asm volatile("ldmatrix.sync.aligned.m8n8.x2.shared.b16 {%0,%1}, [%2];" \
                 : "=r"(r0), "=r"(r1) : "r"(addr))

#define MMA_BF16(c, a0, a1, a2, a3, b0, b1) \
    asm volatile("mma.sync.aligned.m16n8k16.row.col.f32.bf16.bf16.f32 " \
                 "{%0,%1,%2,%3}, {%4,%5,%6,%7}, {%8,%9}, {%0,%1,%2,%3};" \
                 : "+f"((c)[0]), "+f"((c)[1]), "+f"((c)[2]), "+f"((c)[3]) \
                 : "r"(a0), "r"(a1), "r"(a2), "r"(a3), "r"(b0), "r"(b1))

#define MMA_TF32(c, a0, a1, a2, a3, b0, b1) \
    asm volatile("mma.sync.aligned.m16n8k8.row.col.f32.tf32.tf32.f32 " \
                 "{%0,%1,%2,%3}, {%4,%5,%6,%7}, {%8,%9}, {%0,%1,%2,%3};" \
                 : "+f"((c)[0]), "+f"((c)[1]), "+f"((c)[2]), "+f"((c)[3]) \
                 : "r"(a0), "r"(a1), "r"(a2), "r"(a3), "r"(b0), "r"(b1))

__device__ __forceinline__ uint32_t f2tf(float f) {
    uint32_t r;
    asm("cvt.rna.tf32.f32 %0, %1;" : "=r"(r) : "f"(f));
    return r;
}
__device__ __forceinline__ unsigned short bf16hi(float x) {
    return __bfloat16_as_ushort(__float2bfloat16(x));
}

// ---------------- utility kernels ----------------
__global__ void init_state_kernel(const float* __restrict__ hidden,
                                  const float* __restrict__ cell) {
    int i = blockIdx.x * blockDim.x + threadIdx.x;
    if (i == 0) g_barcnt = 0u;
    if (i < 2 * BATCH * HH) { g_h[i] = hidden[i]; g_c[i] = cell[i]; }
}

__global__ void tail_copy_kernel(float* __restrict__ out) {
    int i = blockIdx.x * blockDim.x + threadIdx.x;
    const long long OFF = (long long)BATCH * TT * VV;
    if (i < 2 * BATCH * HH) {
        out[OFF + i] = g_h[i];
        out[OFF + 2 * BATCH * HH + i] = g_c[i];
    }
}

__global__ void embed_kernel(const int* __restrict__ tgt,
                             const float* __restrict__ emb) {
    int blk = blockIdx.x;             // b*TT + t
    int b = blk >> 6, t = blk & 63;
    int idx = tgt[blk];
    int e = threadIdx.x * 4;
    float4 v;
    if (idx == 0) { v.x = v.y = v.z = v.w = 0.f; }
    else v = *reinterpret_cast<const float4*>(emb + (long long)idx * EE + e);
    *reinterpret_cast<float4*>(g_embF + (long long)(t * 32 + b) * 512 + e) = v;
}

__global__ void split_bf16_kernel(const float4* __restrict__ in,
                                  uint2* __restrict__ hi, uint2* __restrict__ lo, int n4) {
    for (int i = blockIdx.x * blockDim.x + threadIdx.x; i < n4; i += gridDim.x * blockDim.x) {
        float4 x = in[i];
        unsigned short h0 = bf16hi(x.x), h1 = bf16hi(x.y), h2 = bf16hi(x.z), h3 = bf16hi(x.w);
        unsigned short l0 = bf16hi(x.x - __bfloat162float(__ushort_as_bfloat16(h0)));
        unsigned short l1 = bf16hi(x.y - __bfloat162float(__ushort_as_bfloat16(h1)));
        unsigned short l2 = bf16hi(x.z - __bfloat162float(__ushort_as_bfloat16(h2)));
        unsigned short l3 = bf16hi(x.w - __bfloat162float(__ushort_as_bfloat16(h3)));
        uint2 hv, lv;
        hv.x = (uint32_t)h0 | ((uint32_t)h1 << 16);
        hv.y = (uint32_t)h2 | ((uint32_t)h3 << 16);
        lv.x = (uint32_t)l0 | ((uint32_t)l1 << 16);
        lv.y = (uint32_t)l2 | ((uint32_t)l3 << 16);
        hi[i] = hv; lo[i] = lv;
    }
}

// pack W[n][k] -> tf32 dual fragments. grid (nt, 2), block 1024.
__global__ void pack_tf32_kernel(const float* __restrict__ W, int sw,
                                 uint4* __restrict__ dst) {
    int nt = blockIdx.x;
    int ki = blockIdx.y * 32 + (threadIdx.x >> 5);
    int lane = threadIdx.x & 31;
    int n = nt * 8 + (lane >> 2);
    int k = ki * 8 + (lane & 3);
    const float* w = W + (long long)n * sw + k;
    float v0 = w[0], v1 = w[4];
    uint4 o;
    o.x = f2tf(v0);
    o.y = f2tf(v1);
    o.z = f2tf(v0 - __uint_as_float(o.x));
    o.w = f2tf(v1 - __uint_as_float(o.y));
    dst[(nt * 64 + ki) * 32 + lane] = o;
}

// pack W^T (acts as W'[n][k] = W[k][n])
__global__ void pack_tf32_t_kernel(const float* __restrict__ W, int sw,
                                   uint4* __restrict__ dst) {
    int nt = blockIdx.x;
    int ki = blockIdx.y * 32 + (threadIdx.x >> 5);
    int lane = threadIdx.x & 31;
    int n = nt * 8 + (lane >> 2);
    int k = ki * 8 + (lane & 3);
    float v0 = W[(long long)k * sw + n];
    float v1 = W[(long long)(k + 4) * sw + n];
    uint4 o;
    o.x = f2tf(v0);
    o.y = f2tf(v1);
    o.z = f2tf(v0 - __uint_as_float(o.x));
    o.w = f2tf(v1 - __uint_as_float(o.y));
    dst[(nt * 64 + ki) * 32 + lane] = o;
}

// ---------------- warp-level M=32 x N=32 3xTF32 mma tile ----------------
// C[32, n0:n0+32] = A[32 x 512 fp32] @ Wpk^T over k8 range [k80, k80+nk8)
__device__ __forceinline__ void mma_row32_t32(
    const float* __restrict__ A,
    const uint4* __restrict__ wpk, int nt0, int k80, int nk8,
    float* __restrict__ C, int ldc, int n0, int lane)
{
    float acc[2][4][4];
    #pragma unroll
    for (int mi = 0; mi < 2; mi++)
        #pragma unroll
        for (int nj = 0; nj < 4; nj++)
            #pragma unroll
            for (int v = 0; v < 4; v++) acc[mi][nj][v] = 0.f;

    const int r = lane >> 2;
    const int cc = lane & 3;
    const float* pa = A + r * 512 + k80 * 8 + cc;
    const uint4* wp = wpk + (nt0 * 64 + k80) * 32 + lane;

    #pragma unroll 2
    for (int kk = 0; kk < nk8; kk++) {
        uint32_t aH[2][4], aL[2][4];
        #pragma unroll
        for (int mi = 0; mi < 2; mi++) {
            const float* p = pa + mi * 16 * 512;
            float f0 = __ldcg(p);
            float f1 = __ldcg(p + 8 * 512);
            float f2 = __ldcg(p + 4);
            float f3 = __ldcg(p + 8 * 512 + 4);
            aH[mi][0] = f2tf(f0); aL[mi][0] = f2tf(f0 - __uint_as_float(aH[mi][0]));
            aH[mi][1] = f2tf(f1); aL[mi][1] = f2tf(f1 - __uint_as_float(aH[mi][1]));
            aH[mi][2] = f2tf(f2); aL[mi][2] = f2tf(f2 - __uint_as_float(aH[mi][2]));
            aH[mi][3] = f2tf(f3); aL[mi][3] = f2tf(f3 - __uint_as_float(aH[mi][3]));
        }
        #pragma unroll
        for (int nj = 0; nj < 4; nj++) {
            uint4 b = __ldg(wp + nj * 2048);
            #pragma unroll
            for (int mi = 0; mi < 2; mi++) {
                MMA_TF32(acc[mi][nj], aH[mi][0], aH[mi][1], aH[mi][2], aH[mi][3], b.x, b.y);
                MMA_TF32(acc[mi][nj], aL[mi][0], aL[mi][1], aL[mi][2], aL[mi][3], b.x, b.y);
                MMA_TF32(acc[mi][nj], aH[mi][0], aH[mi][1], aH[mi][2], aH[mi][3], b.z, b.w);
            }
        }
        pa += 8; wp += 32;
    }
    const int sc2 = cc * 2;
    #pragma unroll
    for (int mi = 0; mi < 2; mi++)
        #pragma unroll
        for (int nj = 0; nj < 4; nj++) {
            int col = n0 + nj * 8 + sc2;
            *reinterpret_cast<float2*>(C + (mi * 16 + r) * ldc + col) =
                make_float2(acc[mi][nj][0], acc[mi][nj][1]);
            *reinterpret_cast<float2*>(C + (mi * 16 + 8 + r) * ldc + col) =
                make_float2(acc[mi][nj][2], acc[mi][nj][3]);
        }
}

// embpre: [2048,2048] = emb @ Wih0[:, :512]^T
__global__ __launch_bounds__(256)
void embpre_mma_kernel() {
    int g = blockIdx.x * 8 + (threadIdx.x >> 5);
    int lane = threadIdx.x & 31;
    int rb = g >> 6;
    int nt = g & 63;
    mma_row32_t32(g_embF + rb * 32 * 512,
                  g_pkIH0, nt * 4, 0, 64,
                  g_embpre + (long long)rb * 32 * 2048, 2048, nt * 32, lane);
}

// encproj: [2048,512] = enc_flat @ W_a
__global__ __launch_bounds__(256)
void encproj_mma_kernel(const float* __restrict__ enc) {
    int g = blockIdx.x * 8 + (threadIdx.x >> 5);   // 0..1023
    int lane = threadIdx.x & 31;
    int rb = g >> 4;
    int nt = g & 15;
    mma_row32_t32(enc + (long long)rb * 32 * 512,
                  g_pkWaT, nt * 4, 0, 64,
                  g_encproj + (long long)rb * 32 * 512, 512, nt * 32, lane);
}

// ---------------- persistent recurrence (5 barriers/step) ----------------
__device__ __forceinline__ float sigmf(float x) { return 1.f / (1.f + expf(-x)); }

__global__ __launch_bounds__(256, 1)
void decoder_persistent(const float* __restrict__ enc,
                        const float* __restrict__ b_ih0,
                        const float* __restrict__ b_hh0,
                        const float* __restrict__ b_ih1,
                        const float* __restrict__ b_hh1) {
    __shared__ float h1s[512];
    __shared__ float sc[64];
    __shared__ float s_red[2];

    const int cta = blockIdx.x;
    const int tid = threadIdx.x;
    const int lane = tid & 31;
    const int wid = tid >> 5;
    unsigned bar_t = 0;

    auto gbar = [&]() {
        __syncthreads();
        __threadfence();
        bar_t += NCTA;
        if (tid == 0) {
            atomicAdd(&g_barcnt, 1u);
            while (*(volatile unsigned*)&g_barcnt < bar_t) { }
        }
        __syncthreads();
    };

    for (int t = 0; t < TT; t++) {
        float* feat_t = g_feat + t * 32768;
        const float* ep = g_embpre + (long long)t * 65536;

        // ==== Phase A: attention (CTA 0-31) || g0hh, g1hh GEMMs (CTA 32-95)
        if (cta < 32) {
            const int b = cta;
            #pragma unroll
            for (int r = 0; r < 2; r++) {
                int k = tid + r * 256;
                h1s[k] = __ldcg(g_h + 16384 + b * 512 + k);
            }
            __syncthreads();
            const float* epj = g_encproj + (long long)b * 64 * 512;
            #pragma unroll
            for (int si = 0; si < 8; si++) {
                int s = wid * 8 + si;
                const float* row = epj + s * 512;
                float sum = 0.f;
                for (int j = lane; j < 512; j += 32) sum += row[j] * h1s[j];
                #pragma unroll
                for (int o = 16; o; o >>= 1) sum += __shfl_down_sync(0xffffffffu, sum, o);
                if (lane == 0) sc[s] = sum;
            }
            __syncthreads();
            if (tid == 0) {
                float mx = sc[0];
                for (int s = 1; s < 64; s++) mx = fmaxf(mx, sc[s]);
                s_red[0] = mx;
            }
            __syncthreads();
            if (tid < 64) sc[tid] = expf(sc[tid] - s_red[0]);
            __syncthreads();
            if (tid == 0) {
                float sm = 0.f;
                for (int s = 0; s < 64; s++) sm += sc[s];
                s_red[1] = 1.f / sm;
            }
            __syncthreads();
            const float inv = s_red[1];
            const float* encb = enc + (long long)b * SS * 512;
            for (int k = tid; k < 512; k += 256) {
                float acc = 0.f;
                #pragma unroll 8
                for (int s = 0; s < 64; s++) acc += sc[s] * encb[s * 512 + k];
                float cv = acc * inv;
                feat_t[b * 1024 + 512 + k] = cv;
                g_ctxF[b * 512 + k] = cv;
            }
        } else {
            int g2 = (cta - 32) * 8 + wid;         // 0..895
            if (g2 < 256) {
                int nt_ = g2 >> 2, ks = g2 & 3;
                mma_row32_t32(g_h, g_pkHH0, nt_ * 4, ks * 16, 16,
                              g_g0hh + ks * 65536, 2048, nt_ * 32, lane);
            } else if (g2 < 512) {
                int g3 = g2 - 256;
                int nt_ = g3 >> 2, ks = g3 & 3;
                mma_row32_t32(g_h + 16384, g_pkHH1, nt_ * 4, ks * 16, 16,
                              g_g1hh + ks * 65536, 2048, nt_ * 32, lane);
            }
        }
        gbar();

        // ==== Phase B: g0ctx = ctx @ Wihc^T (512 warps, ksplit 8) ====
        {
            int g = cta * 8 + wid;
            if (g < 512) {
                int nt_ = g >> 3, ks = g & 7;
                mma_row32_t32(g_ctxF, g_pkIHC, nt_ * 4, ks * 8, 8,
                              g_g0ctx + ks * 65536, 2048, nt_ * 32, lane);
            }
        }
        gbar();

        // ==== Phase C: LSTM0 update ====
        {
            int idx = cta * 256 + tid;
            if (idx < 16384) {
                int b = idx >> 9, u = idx & 511;
                int gg0 = b * 2048 + u;
                float gv[4];
                #pragma unroll
                for (int q = 0; q < 4; q++) {
                    int o = gg0 + q * 512;
                    float v = ep[o];
                    #pragma unroll
                    for (int s = 0; s < 4; s++) v += __ldcg(g_g0hh + s * 65536 + o);
                    #pragma unroll
                    for (int s = 0; s < 8; s++) v += __ldcg(g_g0ctx + s * 65536 + o);
                    gv[q] = v + __ldg(b_ih0 + q * 512 + u) + __ldg(b_hh0 + q * 512 + u);
                }
                float cv = g_c[idx];
                float cn = sigmf(gv[1]) * cv + sigmf(gv[0]) * tanhf(gv[2]);
                float hn = sigmf(gv[3]) * tanhf(cn);
                g_c[idx] = cn;
                g_h[idx] = hn;
            }
        }
        gbar();

        // ==== Phase D: g1ih = h0 @ Wih1^T (512 warps, ksplit 8) ====
        {
            int g = cta * 8 + wid;
            if (g < 512) {
                int nt_ = g >> 3, ks = g & 7;
                mma_row32_t32(g_h, g_pkIH1, nt_ * 4, ks * 8, 8,
                              g_g1ih + ks * 65536, 2048, nt_ * 32, lane);
            }
        }
        gbar();

        // ==== Phase E: LSTM1 update + feat write ====
        {
            int idx = cta * 256 + tid;
            if (idx < 16384) {
                int b = idx >> 9, u = idx & 511;
                int gg0 = b * 2048 + u;
                float gv[4];
                #pragma unroll
                for (int q = 0; q < 4; q++) {
                    int o = gg0 + q * 512;
                    float v = 0.f;
                    #pragma unroll
                    for (int s = 0; s < 4; s++) v += __ldcg(g_g1hh + s * 65536 + o);
                    #pragma unroll
                    for (int s = 0; s < 8; s++) v += __ldcg(g_g1ih + s * 65536 + o);
                    gv[q] = v + __ldg(b_ih1 + q * 512 + u) + __ldg(b_hh1 + q * 512 + u);
                }
                float cv = g_c[16384 + idx];
                float cn = sigmf(gv[1]) * cv + sigmf(gv[0]) * tanhf(gv[2]);
                float hn = sigmf(gv[3]) * tanhf(cn);
                g_c[16384 + idx] = cn;
                g_h[16384 + idx] = hn;
                feat_t[b * 1024 + u] = hn;
            }
        }
        gbar();
    }
}

// ---------------- big projection GEMM (3-term bf16, unchanged) ----------------
#define GK 1024
#define KC 32
#define NKC (GK / KC)
#define RST 40
#define BUF_BF16 (128 * RST)
#define STAGE_BF16 (4 * BUF_BF16)
#define GEMM_SMEM (2 * STAGE_BF16 * 2)

__global__ __launch_bounds__(256, 1)
void big_gemm_mma(const __nv_bfloat16* __restrict__ AH, const __nv_bfloat16* __restrict__ AL,
                  const __nv_bfloat16* __restrict__ BH, const __nv_bfloat16* __restrict__ BL,
                  const float* __restrict__ bias, float* __restrict__ out) {
    extern __shared__ __nv_bfloat16 sm[];
    const int tid = threadIdx.x;
    const int lane = tid & 31;
    const int wid = tid >> 5;
    const int wm = wid >> 1;
    const int wn = wid & 1;
    const int m0 = blockIdx.x * 128;
    const int n0 = blockIdx.y * 128;
    const uint32_t smem_base = smem_to_u32(sm);

    float acc[2][8][4];
    #pragma unroll
    for (int i = 0; i < 2; i++)
        #pragma unroll
        for (int j = 0; j < 8; j++)
            #pragma unroll
            for (int v = 0; v < 4; v++) acc[i][j][v] = 0.f;

    auto load_stage = [&](int st, int kc) {
        const uint32_t sb = smem_base + st * STAGE_BF16 * 2;
        const int k0 = kc * KC;
        #pragma unroll
        for (int r = 0; r < 2; r++) {
            int idx = tid + r * 256;
            int row = idx >> 2, c = idx & 3;
            uint32_t doff = (uint32_t)(row * RST + c * 8) * 2;
            long long aoff = (long long)(m0 + row) * GK + k0 + c * 8;
            long long boff = (long long)(n0 + row) * GK + k0 + c * 8;
            CP16(sb + doff,                AH + aoff);
            CP16(sb + BUF_BF16 * 2 + doff, AL + aoff);
            CP16(sb + BUF_BF16 * 4 + doff, BH + boff);
            CP16(sb + BUF_BF16 * 6 + doff, BL + boff);
        }
        CP_COMMIT();
    };

    load_stage(0, 0);

    for (int kc = 0; kc < NKC; kc++) {
        const int st = kc & 1;
        if (kc + 1 < NKC) { load_stage(st ^ 1, kc + 1); CP_WAIT1(); }
        else              { CP_WAIT0(); }
        __syncthreads();

        const uint32_t sb = smem_base + st * STAGE_BF16 * 2;
        uint32_t ah[2][2][4], al[2][2][4];
        #pragma unroll
        for (int i = 0; i < 2; i++)
            #pragma unroll
            for (int kk = 0; kk < 2; kk++) {
                uint32_t addr = sb + (uint32_t)((wm * 32 + i * 16 + (lane & 15)) * RST
                                                + kk * 16 + (lane >> 4) * 8) * 2;
                LDSM_X4(ah[i][kk][0], ah[i][kk][1], ah[i][kk][2], ah[i][kk][3], addr);
                LDSM_X4(al[i][kk][0], al[i][kk][1], al[i][kk][2], al[i][kk][3],
                        addr + BUF_BF16 * 2);
            }
        #pragma unroll
        for (int j = 0; j < 8; j++) {
            #pragma unroll
            for (int kk = 0; kk < 2; kk++) {
                uint32_t baddr = sb + BUF_BF16 * 4
                    + (uint32_t)((wn * 64 + j * 8 + (lane & 7)) * RST
                                 + kk * 16 + ((lane >> 3) & 1) * 8) * 2;
                uint32_t bh0, bh1, bl0, bl1;
                LDSM_X2(bh0, bh1, baddr);
                LDSM_X2(bl0, bl1, baddr + BUF_BF16 * 2);
                #pragma unroll
                for (int i = 0; i < 2; i++) {
                    MMA_BF16(acc[i][j], ah[i][kk][0], ah[i][kk][1], ah[i][kk][2], ah[i][kk][3], bh0, bh1);
                    MMA_BF16(acc[i][j], al[i][kk][0], al[i][kk][1], al[i][kk][2], al[i][kk][3], bh0, bh1);
                    MMA_BF16(acc[i][j], ah[i][kk][0], ah[i][kk][1], ah[i][kk][2], ah[i][kk][3], bl0, bl1);
                }
            }
        }
        __syncthreads();
    }

    #pragma unroll
    for (int i = 0; i < 2; i++) {
        int mA = m0 + wm * 32 + i * 16 + (lane >> 2);
        int mB = mA + 8;
        int tA = mA >> 5, bA = mA & 31;
        int tB = mB >> 5, bB = mB & 31;
        float* rowA = out + (long long)((bA << 6) + tA) * VV;
        float* rowB = out + (long long)((bB << 6) + tB) * VV;
        #pragma unroll
        for (int j = 0; j < 8; j++) {
            int n = n0 + wn * 64 + j * 8 + (lane & 3) * 2;
            float bv0 = bias[n], bv1 = bias[n + 1];
            float2 vA = make_float2(acc[i][j][0] + bv0, acc[i][j][1] + bv1);
            float2 vB = make_float2(acc[i][j][2] + bv0, acc[i][j][3] + bv1);
            *reinterpret_cast<float2*>(rowA + n) = vA;
            *reinterpret_cast<float2*>(rowB + n) = vB;
        }
    }
}

// ---------------- host launcher ----------------
extern "C" void kernel_launch(void* const* d_in, const int* in_sizes, int n_in,
                              void* d_out, int out_size) {
    const int*   tgt    = (const int*)  d_in[0];
    const float* enc    = (const float*)d_in[1];
    const float* hidden = (const float*)d_in[2];
    const float* cell   = (const float*)d_in[3];
    const float* emb    = (const float*)d_in[4];
    const float* W_a    = (const float*)d_in[5];
    const float* W_ih0  = (const float*)d_in[6];
    const float* W_hh0  = (const float*)d_in[7];
    const float* b_ih0  = (const float*)d_in[8];
    const float* b_hh0  = (const float*)d_in[9];
    const float* W_ih1  = (const float*)d_in[10];
    const float* W_hh1  = (const float*)d_in[11];
    const float* b_ih1  = (const float*)d_in[12];
    const float* b_hh1  = (const float*)d_in[13];
    const float* W_out  = (const float*)d_in[14];
    const float* b_out  = (const float*)d_in[15];
    float* out = (float*)d_out;

    float *p_feat;
    __nv_bfloat16 *p_WH, *p_WL, *p_fH, *p_fL;
    uint4 *pkWaT, *pkHH0, *pkHH1, *pkIH1, *pkIHC, *pkIH0;
    cudaGetSymbolAddress((void**)&p_feat, g_feat);
    cudaGetSymbolAddress((void**)&p_WH,   g_WH);
    cudaGetSymbolAddress((void**)&p_WL,   g_WL);
    cudaGetSymbolAddress((void**)&p_fH,   g_fH);
    cudaGetSymbolAddress((void**)&p_fL,   g_fL);
    cudaGetSymbolAddress((void**)&pkWaT,  g_pkWaT);
    cudaGetSymbolAddress((void**)&pkHH0,  g_pkHH0);
    cudaGetSymbolAddress((void**)&pkHH1,  g_pkHH1);
    cudaGetSymbolAddress((void**)&pkIH1,  g_pkIH1);
    cudaGetSymbolAddress((void**)&pkIHC,  g_pkIHC);
    cudaGetSymbolAddress((void**)&pkIH0,  g_pkIH0);

    init_state_kernel<<<64, 512>>>(hidden, cell);
    embed_kernel<<<BATCH * TT, 128>>>(tgt, emb);

    // pack weights as tf32 duals
    pack_tf32_t_kernel<<<dim3(64, 2),  1024>>>(W_a,        512,  pkWaT);
    pack_tf32_kernel<<<dim3(256, 2), 1024>>>(W_hh0,        512,  pkHH0);
    pack_tf32_kernel<<<dim3(256, 2), 1024>>>(W_hh1,        512,  pkHH1);
    pack_tf32_kernel<<<dim3(256, 2), 1024>>>(W_ih1,        512,  pkIH1);
    pack_tf32_kernel<<<dim3(256, 2), 1024>>>(W_ih0 + 512,  1024, pkIHC);
    pack_tf32_kernel<<<dim3(256, 2), 1024>>>(W_ih0,        1024, pkIH0);

    // precompute emb @ Wih0[:, :512]^T and enc @ W_a
    embpre_mma_kernel<<<512, 256>>>();
    encproj_mma_kernel<<<128, 256>>>(enc);

    // fused persistent recurrence
    decoder_persistent<<<NCTA, 256>>>(enc, b_ih0, b_hh0, b_ih1, b_hh1);

    // split W_out and feat for big GEMM
    split_bf16_kernel<<<4096, 256>>>((const float4*)W_out, (uint2*)p_WH, (uint2*)p_WL,
                                     VV * 1024 / 4);
    split_bf16_kernel<<<2048, 256>>>((const float4*)p_feat, (uint2*)p_fH, (uint2*)p_fL,
                                     2048 * 1024 / 4);

    // tensor-core projection
    cudaFuncSetAttribute(big_gemm_mma, cudaFuncAttributeMaxDynamicSharedMemorySize, GEMM_SMEM);
    big_gemm_mma<<<dim3(16, VV / 128), 256, GEMM_SMEM>>>(p_fH, p_fL, p_WH, p_WL, b_out, out);

    tail_copy_kernel<<<64, 512>>>(out);
}

// round 9
// speedup vs baseline: 1.0525x; 1.0525x over previous
#include <cuda_runtime.h>
#include <cuda_bf16.h>
#include <math.h>
#include <stdint.h>

// Problem constants
#define BATCH 32
#define TT 64
#define SS 64
#define VV 32000
#define EE 512
#define HH 512
#define NCTA 144

// ---------------- device scratch ----------------
__device__ float g_embF[2048 * 512];             // embedded fp32, row = t*32+b
__device__ float g_encproj[2048 * 512];          // enc @ W_a, row = b*64+s
__device__ float g_encIHC[2048 * 2048];          // enc @ Wih0[:,512:]^T, row = b*64+s
__device__ float g_h[2 * BATCH * HH];            // fp32 state
__device__ float g_c[2 * BATCH * HH];
__device__ float g_feat[TT * BATCH * 1024];      // [t][b][ h1 | ctx ]
__device__ float g_embpre[TT * BATCH * 2048];    // emb @ Wih0[:, :512]^T
__device__ float g_g0hh[4 * BATCH * 2048];
__device__ float g_g1hh[4 * BATCH * 2048];
__device__ float g_g0ctx[BATCH * 2048];          // attn @ encIHC (single buffer)
__device__ float g_g1ih[8 * BATCH * 2048];
__device__ unsigned g_barcnt;
// packed tf32 weights: [nt8][ki8(64)][lane32] uint4{bH0,bH1,bL0,bL1}
__device__ uint4 g_pkWaT[64 * 64 * 32];          // W_a^T (for encproj)
__device__ uint4 g_pkHH0[256 * 64 * 32];
__device__ uint4 g_pkHH1[256 * 64 * 32];
__device__ uint4 g_pkIH1[256 * 64 * 32];
__device__ uint4 g_pkIHC[256 * 64 * 32];
__device__ uint4 g_pkIH0[256 * 64 * 32];
// bf16 split operands for big projection GEMM
__device__ __nv_bfloat16 g_WH[VV * 1024];
__device__ __nv_bfloat16 g_WL[VV * 1024];
__device__ __nv_bfloat16 g_fH[2048 * 1024];
__device__ __nv_bfloat16 g_fL[2048 * 1024];

// ---------------- PTX helpers ----------------
__device__ __forceinline__ uint32_t smem_to_u32(const void* p) {
    uint32_t a;
    asm("{ .reg .u64 t; cvta.to.shared.u64 t, %1; cvt.u32.u64 %0, t; }" : "=r"(a) : "l"(p));
    return a;
}
#define CP16(dst, src) \
    asm volatile("cp.async.cg.shared.global [%0], [%1], 16;" \
                 :: "r"(dst), "l"(src) : "memory")
#define CP_COMMIT() asm volatile("cp.async.commit_group;" ::: "memory")
#define CP_WAIT0()  asm volatile("cp.async.wait_group 0;" ::: "memory")
#define CP_WAIT1()  asm volatile("cp.async.wait_group 1;" ::: "memory")

#define LDSM_X4(r0, r1, r2, r3, addr) \
    asm volatile("ldmatrix.sync.aligned.m8n8.x4.shared.b16 {%0,%1,%2,%3}, [%4];" \
                 : "=r"(r0), "=r"(r1), "=r"(r2), "=r"(r3) : "r"(addr))
#define LDSM_X2(r0, r1, addr) \
    asm volatile("ldmatrix.sync.aligned.m8n8.x2.shared.b16 {%0,%1}, [%2];" \
                 : "=r"(r0), "=r"(r1) : "r"(addr))

#define MMA_BF16(c, a0, a1, a2, a3, b0, b1) \
    asm volatile("mma.sync.aligned.m16n8k16.row.col.f32.bf16.bf16.f32 " \
                 "{%0,%1,%2,%3}, {%4,%5,%6,%7}, {%8,%9}, {%0,%1,%2,%3};" \
                 : "+f"((c)[0]), "+f"((c)[1]), "+f"((c)[2]), "+f"((c)[3]) \
                 : "r"(a0), "r"(a1), "r"(a2), "r"(a3), "r"(b0), "r"(b1))

#define MMA_TF32(c, a0, a1, a2, a3, b0, b1) \
    asm volatile("mma.sync.aligned.m16n8k8.row.col.f32.tf32.tf32.f32 " \
                 "{%0,%1,%2,%3}, {%4,%5,%6,%7}, {%8,%9}, {%0,%1,%2,%3};" \
                 : "+f"((c)[0]), "+f"((c)[1]), "+f"((c)[2]), "+f"((c)[3]) \
                 : "r"(a0), "r"(a1), "r"(a2), "r"(a3), "r"(b0), "r"(b1))

__device__ __forceinline__ uint32_t f2tf(float f) {
    uint32_t r;
    asm("cvt.rna.tf32.f32 %0, %1;" : "=r"(r) : "f"(f));
    return r;
}
__device__ __forceinline__ unsigned short bf16hi(float x) {
    return __bfloat16_as_ushort(__float2bfloat16(x));
}

// ---------------- utility kernels ----------------
__global__ void init_state_kernel(const float* __restrict__ hidden,
                                  const float* __restrict__ cell) {
    int i = blockIdx.x * blockDim.x + threadIdx.x;
    if (i == 0) g_barcnt = 0u;
    if (i < 2 * BATCH * HH) { g_h[i] = hidden[i]; g_c[i] = cell[i]; }
}

__global__ void tail_copy_kernel(float* __restrict__ out) {
    int i = blockIdx.x * blockDim.x + threadIdx.x;
    const long long OFF = (long long)BATCH * TT * VV;
    if (i < 2 * BATCH * HH) {
        out[OFF + i] = g_h[i];
        out[OFF + 2 * BATCH * HH + i] = g_c[i];
    }
}

__global__ void embed_kernel(const int* __restrict__ tgt,
                             const float* __restrict__ emb) {
    int blk = blockIdx.x;             // b*TT + t
    int b = blk >> 6, t = blk & 63;
    int idx = tgt[blk];
    int e = threadIdx.x * 4;
    float4 v;
    if (idx == 0) { v.x = v.y = v.z = v.w = 0.f; }
    else v = *reinterpret_cast<const float4*>(emb + (long long)idx * EE + e);
    *reinterpret_cast<float4*>(g_embF + (long long)(t * 32 + b) * 512 + e) = v;
}

__global__ void split_bf16_kernel(const float4* __restrict__ in,
                                  uint2* __restrict__ hi, uint2* __restrict__ lo, int n4) {
    for (int i = blockIdx.x * blockDim.x + threadIdx.x; i < n4; i += gridDim.x * blockDim.x) {
        float4 x = in[i];
        unsigned short h0 = bf16hi(x.x), h1 = bf16hi(x.y), h2 = bf16hi(x.z), h3 = bf16hi(x.w);
        unsigned short l0 = bf16hi(x.x - __bfloat162float(__ushort_as_bfloat16(h0)));
        unsigned short l1 = bf16hi(x.y - __bfloat162float(__ushort_as_bfloat16(h1)));
        unsigned short l2 = bf16hi(x.z - __bfloat162float(__ushort_as_bfloat16(h2)));
        unsigned short l3 = bf16hi(x.w - __bfloat162float(__ushort_as_bfloat16(h3)));
        uint2 hv, lv;
        hv.x = (uint32_t)h0 | ((uint32_t)h1 << 16);
        hv.y = (uint32_t)h2 | ((uint32_t)h3 << 16);
        lv.x = (uint32_t)l0 | ((uint32_t)l1 << 16);
        lv.y = (uint32_t)l2 | ((uint32_t)l3 << 16);
        hi[i] = hv; lo[i] = lv;
    }
}

// pack W[n][k] -> tf32 dual fragments. grid (nt, 2), block 1024.
__global__ void pack_tf32_kernel(const float* __restrict__ W, int sw,
                                 uint4* __restrict__ dst) {
    int nt = blockIdx.x;
    int ki = blockIdx.y * 32 + (threadIdx.x >> 5);
    int lane = threadIdx.x & 31;
    int n = nt * 8 + (lane >> 2);
    int k = ki * 8 + (lane & 3);
    const float* w = W + (long long)n * sw + k;
    float v0 = w[0], v1 = w[4];
    uint4 o;
    o.x = f2tf(v0);
    o.y = f2tf(v1);
    o.z = f2tf(v0 - __uint_as_float(o.x));
    o.w = f2tf(v1 - __uint_as_float(o.y));
    dst[(nt * 64 + ki) * 32 + lane] = o;
}

// pack W^T (acts as W'[n][k] = W[k][n])
__global__ void pack_tf32_t_kernel(const float* __restrict__ W, int sw,
                                   uint4* __restrict__ dst) {
    int nt = blockIdx.x;
    int ki = blockIdx.y * 32 + (threadIdx.x >> 5);
    int lane = threadIdx.x & 31;
    int n = nt * 8 + (lane >> 2);
    int k = ki * 8 + (lane & 3);
    float v0 = W[(long long)k * sw + n];
    float v1 = W[(long long)(k + 4) * sw + n];
    uint4 o;
    o.x = f2tf(v0);
    o.y = f2tf(v1);
    o.z = f2tf(v0 - __uint_as_float(o.x));
    o.w = f2tf(v1 - __uint_as_float(o.y));
    dst[(nt * 64 + ki) * 32 + lane] = o;
}

// ---------------- warp-level M=32 x N=32 4xTF32 mma tile ----------------
// C[32, n0:n0+32] = A[32 x 512 fp32] @ Wpk^T over k8 range [k80, k80+nk8)
__device__ __forceinline__ void mma_row32_t32(
    const float* __restrict__ A,
    const uint4* __restrict__ wpk, int nt0, int k80, int nk8,
    float* __restrict__ C, int ldc, int n0, int lane)
{
    float acc[2][4][4];
    #pragma unroll
    for (int mi = 0; mi < 2; mi++)
        #pragma unroll
        for (int nj = 0; nj < 4; nj++)
            #pragma unroll
            for (int v = 0; v < 4; v++) acc[mi][nj][v] = 0.f;

    const int r = lane >> 2;
    const int cc = lane & 3;
    const float* pa = A + r * 512 + k80 * 8 + cc;
    const uint4* wp = wpk + (nt0 * 64 + k80) * 32 + lane;

    #pragma unroll 2
    for (int kk = 0; kk < nk8; kk++) {
        uint32_t aH[2][4], aL[2][4];
        #pragma unroll
        for (int mi = 0; mi < 2; mi++) {
            const float* p = pa + mi * 16 * 512;
            float f0 = __ldcg(p);
            float f1 = __ldcg(p + 8 * 512);
            float f2 = __ldcg(p + 4);
            float f3 = __ldcg(p + 8 * 512 + 4);
            aH[mi][0] = f2tf(f0); aL[mi][0] = f2tf(f0 - __uint_as_float(aH[mi][0]));
            aH[mi][1] = f2tf(f1); aL[mi][1] = f2tf(f1 - __uint_as_float(aH[mi][1]));
            aH[mi][2] = f2tf(f2); aL[mi][2] = f2tf(f2 - __uint_as_float(aH[mi][2]));
            aH[mi][3] = f2tf(f3); aL[mi][3] = f2tf(f3 - __uint_as_float(aH[mi][3]));
        }
        #pragma unroll
        for (int nj = 0; nj < 4; nj++) {
            uint4 b = __ldg(wp + nj * 2048);
            #pragma unroll
            for (int mi = 0; mi < 2; mi++) {
                MMA_TF32(acc[mi][nj], aH[mi][0], aH[mi][1], aH[mi][2], aH[mi][3], b.x, b.y);
                MMA_TF32(acc[mi][nj], aL[mi][0], aL[mi][1], aL[mi][2], aL[mi][3], b.x, b.y);
                MMA_TF32(acc[mi][nj], aH[mi][0], aH[mi][1], aH[mi][2], aH[mi][3], b.z, b.w);
                MMA_TF32(acc[mi][nj], aL[mi][0], aL[mi][1], aL[mi][2], aL[mi][3], b.z, b.w);
            }
        }
        pa += 8; wp += 32;
    }
    const int sc2 = cc * 2;
    #pragma unroll
    for (int mi = 0; mi < 2; mi++)
        #pragma unroll
        for (int nj = 0; nj < 4; nj++) {
            int col = n0 + nj * 8 + sc2;
            *reinterpret_cast<float2*>(C + (mi * 16 + r) * ldc + col) =
                make_float2(acc[mi][nj][0], acc[mi][nj][1]);
            *reinterpret_cast<float2*>(C + (mi * 16 + 8 + r) * ldc + col) =
                make_float2(acc[mi][nj][2], acc[mi][nj][3]);
        }
}

// embpre: [2048,2048] = emb @ Wih0[:, :512]^T
__global__ __launch_bounds__(256)
void embpre_mma_kernel() {
    int g = blockIdx.x * 8 + (threadIdx.x >> 5);
    int lane = threadIdx.x & 31;
    int rb = g >> 6;
    int nt = g & 63;
    mma_row32_t32(g_embF + rb * 32 * 512,
                  g_pkIH0, nt * 4, 0, 64,
                  g_embpre + (long long)rb * 32 * 2048, 2048, nt * 32, lane);
}

// encproj: [2048,512] = enc_flat @ W_a
__global__ __launch_bounds__(256)
void encproj_mma_kernel(const float* __restrict__ enc) {
    int g = blockIdx.x * 8 + (threadIdx.x >> 5);   // 0..1023
    int lane = threadIdx.x & 31;
    int rb = g >> 4;
    int nt = g & 15;
    mma_row32_t32(enc + (long long)rb * 32 * 512,
                  g_pkWaT, nt * 4, 0, 64,
                  g_encproj + (long long)rb * 32 * 512, 512, nt * 32, lane);
}

// encIHC: [2048,2048] = enc_flat @ Wih0[:, 512:]^T
__global__ __launch_bounds__(256)
void encihc_mma_kernel(const float* __restrict__ enc) {
    int g = blockIdx.x * 8 + (threadIdx.x >> 5);
    int lane = threadIdx.x & 31;
    int rb = g >> 6;
    int nt = g & 63;
    mma_row32_t32(enc + (long long)rb * 32 * 512,
                  g_pkIHC, nt * 4, 0, 64,
                  g_encIHC + (long long)rb * 32 * 2048, 2048, nt * 32, lane);
}

// ---------------- persistent recurrence (4 barriers/step) ----------------
__device__ __forceinline__ float sigmf(float x) { return 1.f / (1.f + expf(-x)); }

__global__ __launch_bounds__(256, 1)
void decoder_persistent(const float* __restrict__ enc,
                        const float* __restrict__ b_ih0,
                        const float* __restrict__ b_hh0,
                        const float* __restrict__ b_ih1,
                        const float* __restrict__ b_hh1) {
    __shared__ float h1s[512];
    __shared__ float sc[64];
    __shared__ float s_red[2];

    const int cta = blockIdx.x;
    const int tid = threadIdx.x;
    const int lane = tid & 31;
    const int wid = tid >> 5;
    unsigned bar_t = 0;

    auto gbar = [&]() {
        __syncthreads();
        __threadfence();
        bar_t += NCTA;
        if (tid == 0) {
            atomicAdd(&g_barcnt, 1u);
            while (*(volatile unsigned*)&g_barcnt < bar_t) { }
        }
        __syncthreads();
    };

    for (int t = 0; t < TT; t++) {
        float* feat_t = g_feat + t * 32768;
        const float* ep = g_embpre + (long long)t * 65536;

        // ==== Phase A: attention + g0ctx (CTA 0-31) || g0hh, g1hh (CTA 32-95)
        if (cta < 32) {
            const int b = cta;
            #pragma unroll
            for (int r = 0; r < 2; r++) {
                int k = tid + r * 256;
                h1s[k] = __ldcg(g_h + 16384 + b * 512 + k);
            }
            __syncthreads();
            const float* epj = g_encproj + (long long)b * 64 * 512;
            #pragma unroll
            for (int si = 0; si < 8; si++) {
                int s = wid * 8 + si;
                const float* row = epj + s * 512;
                float sum = 0.f;
                for (int j = lane; j < 512; j += 32) sum += row[j] * h1s[j];
                #pragma unroll
                for (int o = 16; o; o >>= 1) sum += __shfl_down_sync(0xffffffffu, sum, o);
                if (lane == 0) sc[s] = sum;
            }
            __syncthreads();
            if (tid == 0) {
                float mx = sc[0];
                for (int s = 1; s < 64; s++) mx = fmaxf(mx, sc[s]);
                s_red[0] = mx;
            }
            __syncthreads();
            if (tid < 64) sc[tid] = expf(sc[tid] - s_red[0]);
            __syncthreads();
            if (tid == 0) {
                float sm = 0.f;
                for (int s = 0; s < 64; s++) sm += sc[s];
                s_red[1] = 1.f / sm;
            }
            __syncthreads();
            const float inv = s_red[1];

            // ctx: 2 cols/thread from enc
            {
                const float* encb = enc + (long long)b * SS * 512 + tid * 2;
                float c0 = 0.f, c1 = 0.f;
                #pragma unroll 8
                for (int s = 0; s < 64; s++) {
                    float w = sc[s];
                    float2 x = *reinterpret_cast<const float2*>(encb + s * 512);
                    c0 += w * x.x; c1 += w * x.y;
                }
                feat_t[b * 1024 + 512 + tid * 2]     = c0 * inv;
                feat_t[b * 1024 + 512 + tid * 2 + 1] = c1 * inv;
            }
            // g0ctx: 8 cols/thread from encIHC
            {
                const float* eb = g_encIHC + (long long)b * 64 * 2048 + tid * 8;
                float a8[8] = {0.f, 0.f, 0.f, 0.f, 0.f, 0.f, 0.f, 0.f};
                #pragma unroll 4
                for (int s = 0; s < 64; s++) {
                    float w = sc[s];
                    float4 x = *reinterpret_cast<const float4*>(eb + (long long)s * 2048);
                    float4 y = *reinterpret_cast<const float4*>(eb + (long long)s * 2048 + 4);
                    a8[0] += w * x.x; a8[1] += w * x.y; a8[2] += w * x.z; a8[3] += w * x.w;
                    a8[4] += w * y.x; a8[5] += w * y.y; a8[6] += w * y.z; a8[7] += w * y.w;
                }
                float* o = g_g0ctx + b * 2048 + tid * 8;
                #pragma unroll
                for (int j = 0; j < 8; j++) o[j] = a8[j] * inv;
            }
        } else {
            int g2 = (cta - 32) * 8 + wid;         // 0..895
            if (g2 < 256) {
                int nt_ = g2 >> 2, ks = g2 & 3;
                mma_row32_t32(g_h, g_pkHH0, nt_ * 4, ks * 16, 16,
                              g_g0hh + ks * 65536, 2048, nt_ * 32, lane);
            } else if (g2 < 512) {
                int g3 = g2 - 256;
                int nt_ = g3 >> 2, ks = g3 & 3;
                mma_row32_t32(g_h + 16384, g_pkHH1, nt_ * 4, ks * 16, 16,
                              g_g1hh + ks * 65536, 2048, nt_ * 32, lane);
            }
        }
        gbar();

        // ==== Phase C: LSTM0 update ====
        {
            int idx = cta * 256 + tid;
            if (idx < 16384) {
                int b = idx >> 9, u = idx & 511;
                int gg0 = b * 2048 + u;
                float gv[4];
                #pragma unroll
                for (int q = 0; q < 4; q++) {
                    int o = gg0 + q * 512;
                    float v = ep[o] + __ldcg(g_g0ctx + o);
                    #pragma unroll
                    for (int s = 0; s < 4; s++) v += __ldcg(g_g0hh + s * 65536 + o);
                    gv[q] = v + __ldg(b_ih0 + q * 512 + u) + __ldg(b_hh0 + q * 512 + u);
                }
                float cv = g_c[idx];
                float cn = sigmf(gv[1]) * cv + sigmf(gv[0]) * tanhf(gv[2]);
                float hn = sigmf(gv[3]) * tanhf(cn);
                g_c[idx] = cn;
                g_h[idx] = hn;
            }
        }
        gbar();

        // ==== Phase D: g1ih = h0 @ Wih1^T (512 warps, ksplit 8) ====
        {
            int g = cta * 8 + wid;
            if (g < 512) {
                int nt_ = g >> 3, ks = g & 7;
                mma_row32_t32(g_h, g_pkIH1, nt_ * 4, ks * 8, 8,
                              g_g1ih + ks * 65536, 2048, nt_ * 32, lane);
            }
        }
        gbar();

        // ==== Phase E: LSTM1 update + feat write ====
        {
            int idx = cta * 256 + tid;
            if (idx < 16384) {
                int b = idx >> 9, u = idx & 511;
                int gg0 = b * 2048 + u;
                float gv[4];
                #pragma unroll
                for (int q = 0; q < 4; q++) {
                    int o = gg0 + q * 512;
                    float v = 0.f;
                    #pragma unroll
                    for (int s = 0; s < 4; s++) v += __ldcg(g_g1hh + s * 65536 + o);
                    #pragma unroll
                    for (int s = 0; s < 8; s++) v += __ldcg(g_g1ih + s * 65536 + o);
                    gv[q] = v + __ldg(b_ih1 + q * 512 + u) + __ldg(b_hh1 + q * 512 + u);
                }
                float cv = g_c[16384 + idx];
                float cn = sigmf(gv[1]) * cv + sigmf(gv[0]) * tanhf(gv[2]);
                float hn = sigmf(gv[3]) * tanhf(cn);
                g_c[16384 + idx] = cn;
                g_h[16384 + idx] = hn;
                feat_t[b * 1024 + u] = hn;
            }
        }
        gbar();
    }
}

// ---------------- big projection GEMM (3-term bf16, unchanged) ----------------
#define GK 1024
#define KC 32
#define NKC (GK / KC)
#define RST 40
#define BUF_BF16 (128 * RST)
#define STAGE_BF16 (4 * BUF_BF16)
#define GEMM_SMEM (2 * STAGE_BF16 * 2)

__global__ __launch_bounds__(256, 1)
void big_gemm_mma(const __nv_bfloat16* __restrict__ AH, const __nv_bfloat16* __restrict__ AL,
                  const __nv_bfloat16* __restrict__ BH, const __nv_bfloat16* __restrict__ BL,
                  const float* __restrict__ bias, float* __restrict__ out) {
    extern __shared__ __nv_bfloat16 sm[];
    const int tid = threadIdx.x;
    const int lane = tid & 31;
    const int wid = tid >> 5;
    const int wm = wid >> 1;
    const int wn = wid & 1;
    const int m0 = blockIdx.x * 128;
    const int n0 = blockIdx.y * 128;
    const uint32_t smem_base = smem_to_u32(sm);

    float acc[2][8][4];
    #pragma unroll
    for (int i = 0; i < 2; i++)
        #pragma unroll
        for (int j = 0; j < 8; j++)
            #pragma unroll
            for (int v = 0; v < 4; v++) acc[i][j][v] = 0.f;

    auto load_stage = [&](int st, int kc) {
        const uint32_t sb = smem_base + st * STAGE_BF16 * 2;
        const int k0 = kc * KC;
        #pragma unroll
        for (int r = 0; r < 2; r++) {
            int idx = tid + r * 256;
            int row = idx >> 2, c = idx & 3;
            uint32_t doff = (uint32_t)(row * RST + c * 8) * 2;
            long long aoff = (long long)(m0 + row) * GK + k0 + c * 8;
            long long boff = (long long)(n0 + row) * GK + k0 + c * 8;
            CP16(sb + doff,                AH + aoff);
            CP16(sb + BUF_BF16 * 2 + doff, AL + aoff);
            CP16(sb + BUF_BF16 * 4 + doff, BH + boff);
            CP16(sb + BUF_BF16 * 6 + doff, BL + boff);
        }
        CP_COMMIT();
    };

    load_stage(0, 0);

    for (int kc = 0; kc < NKC; kc++) {
        const int st = kc & 1;
        if (kc + 1 < NKC) { load_stage(st ^ 1, kc + 1); CP_WAIT1(); }
        else              { CP_WAIT0(); }
        __syncthreads();

        const uint32_t sb = smem_base + st * STAGE_BF16 * 2;
        uint32_t ah[2][2][4], al[2][2][4];
        #pragma unroll
        for (int i = 0; i < 2; i++)
            #pragma unroll
            for (int kk = 0; kk < 2; kk++) {
                uint32_t addr = sb + (uint32_t)((wm * 32 + i * 16 + (lane & 15)) * RST
                                                + kk * 16 + (lane >> 4) * 8) * 2;
                LDSM_X4(ah[i][kk][0], ah[i][kk][1], ah[i][kk][2], ah[i][kk][3], addr);
                LDSM_X4(al[i][kk][0], al[i][kk][1], al[i][kk][2], al[i][kk][3],
                        addr + BUF_BF16 * 2);
            }
        #pragma unroll
        for (int j = 0; j < 8; j++) {
            #pragma unroll
            for (int kk = 0; kk < 2; kk++) {
                uint32_t baddr = sb + BUF_BF16 * 4
                    + (uint32_t)((wn * 64 + j * 8 + (lane & 7)) * RST
                                 + kk * 16 + ((lane >> 3) & 1) * 8) * 2;
                uint32_t bh0, bh1, bl0, bl1;
                LDSM_X2(bh0, bh1, baddr);
                LDSM_X2(bl0, bl1, baddr + BUF_BF16 * 2);
                #pragma unroll
                for (int i = 0; i < 2; i++) {
                    MMA_BF16(acc[i][j], ah[i][kk][0], ah[i][kk][1], ah[i][kk][2], ah[i][kk][3], bh0, bh1);
                    MMA_BF16(acc[i][j], al[i][kk][0], al[i][kk][1], al[i][kk][2], al[i][kk][3], bh0, bh1);
                    MMA_BF16(acc[i][j], ah[i][kk][0], ah[i][kk][1], ah[i][kk][2], ah[i][kk][3], bl0, bl1);
                }
            }
        }
        __syncthreads();
    }

    #pragma unroll
    for (int i = 0; i < 2; i++) {
        int mA = m0 + wm * 32 + i * 16 + (lane >> 2);
        int mB = mA + 8;
        int tA = mA >> 5, bA = mA & 31;
        int tB = mB >> 5, bB = mB & 31;
        float* rowA = out + (long long)((bA << 6) + tA) * VV;
        float* rowB = out + (long long)((bB << 6) + tB) * VV;
        #pragma unroll
        for (int j = 0; j < 8; j++) {
            int n = n0 + wn * 64 + j * 8 + (lane & 3) * 2;
            float bv0 = bias[n], bv1 = bias[n + 1];
            float2 vA = make_float2(acc[i][j][0] + bv0, acc[i][j][1] + bv1);
            float2 vB = make_float2(acc[i][j][2] + bv0, acc[i][j][3] + bv1);
            *reinterpret_cast<float2*>(rowA + n) = vA;
            *reinterpret_cast<float2*>(rowB + n) = vB;
        }
    }
}

// ---------------- host launcher ----------------
extern "C" void kernel_launch(void* const* d_in, const int* in_sizes, int n_in,
                              void* d_out, int out_size) {
    const int*   tgt    = (const int*)  d_in[0];
    const float* enc    = (const float*)d_in[1];
    const float* hidden = (const float*)d_in[2];
    const float* cell   = (const float*)d_in[3];
    const float* emb    = (const float*)d_in[4];
    const float* W_a    = (const float*)d_in[5];
    const float* W_ih0  = (const float*)d_in[6];
    const float* W_hh0  = (const float*)d_in[7];
    const float* b_ih0  = (const float*)d_in[8];
    const float* b_hh0  = (const float*)d_in[9];
    const float* W_ih1  = (const float*)d_in[10];
    const float* W_hh1  = (const float*)d_in[11];
    const float* b_ih1  = (const float*)d_in[12];
    const float* b_hh1  = (const float*)d_in[13];
    const float* W_out  = (const float*)d_in[14];
    const float* b_out  = (const float*)d_in[15];
    float* out = (float*)d_out;

    float *p_feat;
    __nv_bfloat16 *p_WH, *p_WL, *p_fH, *p_fL;
    uint4 *pkWaT, *pkHH0, *pkHH1, *pkIH1, *pkIHC, *pkIH0;
    cudaGetSymbolAddress((void**)&p_feat, g_feat);
    cudaGetSymbolAddress((void**)&p_WH,   g_WH);
    cudaGetSymbolAddress((void**)&p_WL,   g_WL);
    cudaGetSymbolAddress((void**)&p_fH,   g_fH);
    cudaGetSymbolAddress((void**)&p_fL,   g_fL);
    cudaGetSymbolAddress((void**)&pkWaT,  g_pkWaT);
    cudaGetSymbolAddress((void**)&pkHH0,  g_pkHH0);
    cudaGetSymbolAddress((void**)&pkHH1,  g_pkHH1);
    cudaGetSymbolAddress((void**)&pkIH1,  g_pkIH1);
    cudaGetSymbolAddress((void**)&pkIHC,  g_pkIHC);
    cudaGetSymbolAddress((void**)&pkIH0,  g_pkIH0);

    init_state_kernel<<<64, 512>>>(hidden, cell);
    embed_kernel<<<BATCH * TT, 128>>>(tgt, emb);

    // pack weights as tf32 duals
    pack_tf32_t_kernel<<<dim3(64, 2),  1024>>>(W_a,        512,  pkWaT);
    pack_tf32_kernel<<<dim3(256, 2), 1024>>>(W_hh0,        512,  pkHH0);
    pack_tf32_kernel<<<dim3(256, 2), 1024>>>(W_hh1,        512,  pkHH1);
    pack_tf32_kernel<<<dim3(256, 2), 1024>>>(W_ih1,        512,  pkIH1);
    pack_tf32_kernel<<<dim3(256, 2), 1024>>>(W_ih0 + 512,  1024, pkIHC);
    pack_tf32_kernel<<<dim3(256, 2), 1024>>>(W_ih0,        1024, pkIH0);

    // precompute emb @ Wih0[:, :512]^T, enc @ W_a, enc @ Wih0[:,512:]^T
    embpre_mma_kernel<<<512, 256>>>();
    encproj_mma_kernel<<<128, 256>>>(enc);
    encihc_mma_kernel<<<512, 256>>>(enc);

    // fused persistent recurrence (4 barriers/step)
    decoder_persistent<<<NCTA, 256>>>(enc, b_ih0, b_hh0, b_ih1, b_hh1);

    // split W_out and feat for big GEMM
    split_bf16_kernel<<<4096, 256>>>((const float4*)W_out, (uint2*)p_WH, (uint2*)p_WL,
                                     VV * 1024 / 4);
    split_bf16_kernel<<<2048, 256>>>((const float4*)p_feat, (uint2*)p_fH, (uint2*)p_fL,
                                     2048 * 1024 / 4);

    // tensor-core projection
    cudaFuncSetAttribute(big_gemm_mma, cudaFuncAttributeMaxDynamicSharedMemorySize, GEMM_SMEM);
    big_gemm_mma<<<dim3(16, VV / 128), 256, GEMM_SMEM>>>(p_fH, p_fL, p_WH, p_WL, b_out, out);

    tail_copy_kernel<<<64, 512>>>(out);
}